// round 9
// baseline (speedup 1.0000x reference)
#include <cuda_runtime.h>
#include <cstdint>
#include <math.h>

// Problem constants
#define BB   64
#define TT   128
#define EE   256
#define HH   256
#define BT   (BB*TT)        // 8192

// Scratch: input-drive buffer xp[B*T, HH] (8 MB), reused for level 0 then 1.
__device__ float g_xp[BT * HH];

// ---------------------------------------------------------------------------
// GEMM: g_xp[m, n] = sum_k A[row(m), k] * W[n, k] + bias[n]
// ---------------------------------------------------------------------------
__global__ __launch_bounds__(256) void gemm_xp(
    const float* __restrict__ A, const int* __restrict__ rowidx, int astride,
    const float* __restrict__ W, const float* __restrict__ bias)
{
    __shared__ float As[32][68];
    __shared__ float Bs[32][68];

    const int m0  = blockIdx.x * 64;
    const int n0  = blockIdx.y * 64;
    const int tid = threadIdx.x;
    const int lr  = tid >> 3;
    const int lk  = (tid & 7) << 2;
    const int ty  = tid >> 4;
    const int tx  = tid & 15;

    float acc[4][4] = {};

    for (int k0 = 0; k0 < 256; k0 += 32) {
        #pragma unroll
        for (int rr = 0; rr < 2; rr++) {
            int m  = m0 + lr + rr * 32;
            int ar = rowidx ? rowidx[m] : m;
            float4 a4 = *(const float4*)(A + (size_t)ar * astride + k0 + lk);
            As[lk + 0][lr + rr * 32] = a4.x;
            As[lk + 1][lr + rr * 32] = a4.y;
            As[lk + 2][lr + rr * 32] = a4.z;
            As[lk + 3][lr + rr * 32] = a4.w;

            int n = n0 + lr + rr * 32;
            float4 b4 = *(const float4*)(W + (size_t)n * 256 + k0 + lk);
            Bs[lk + 0][lr + rr * 32] = b4.x;
            Bs[lk + 1][lr + rr * 32] = b4.y;
            Bs[lk + 2][lr + rr * 32] = b4.z;
            Bs[lk + 3][lr + rr * 32] = b4.w;
        }
        __syncthreads();

        #pragma unroll
        for (int kk = 0; kk < 32; kk++) {
            float a[4], b[4];
            *(float4*)a = *(const float4*)&As[kk][ty << 2];
            *(float4*)b = *(const float4*)&Bs[kk][tx << 2];
            #pragma unroll
            for (int i = 0; i < 4; i++)
                #pragma unroll
                for (int jx = 0; jx < 4; jx++)
                    acc[i][jx] = fmaf(a[i], b[jx], acc[i][jx]);
        }
        __syncthreads();
    }

    float4 bv = *(const float4*)(bias + n0 + (tx << 2));
    #pragma unroll
    for (int i = 0; i < 4; i++) {
        int m = m0 + (ty << 2) + i;
        float4 o;
        o.x = acc[i][0] + bv.x;
        o.y = acc[i][1] + bv.y;
        o.z = acc[i][2] + bv.z;
        o.w = acc[i][3] + bv.w;
        *(float4*)(g_xp + (size_t)m * 256 + n0 + (tx << 2)) = o;
    }
}

// ---------------------------------------------------------------------------
// LTC scan: 4-CTA clusters, 32 clusters (128 CTAs), 2 batch elems / cluster.
//   - h stored as interleaved (b0,b1) float pairs; rank block = 64 pairs at
//     stride 132 floats (ks read groups bank-disjoint).
//   - Weights duplicated per k as (w_k,w_k); fma.rn.f32x2 does both batches.
//   - Transport: producers scatter their pair with plain st.shared::cluster
//     (generic proxy, no fence, no engine). After bar.sync, threads 0-3 each
//     issue ONE mbarrier.arrive.release.cluster to one rank. Destination
//     barrier counts 4 arrivals/step -> 4 events (vs 3 bulk copies in R4,
//     vs 256 st.async tx in R8) and NO engine pickup / async fence.
//   - 4 alternating count-barriers + 3-buffer h rotation.
// ---------------------------------------------------------------------------
#define CS   4
#define BLK  132     // floats per rank block: 128 data (64 pairs) + 4 pad

typedef unsigned long long u64t;

__device__ __forceinline__ uint32_t smem_u32(const void* p) {
    return (uint32_t)__cvta_generic_to_shared(p);
}
__device__ __forceinline__ u64t pk2(float x, float y) {
    u64t r; asm("mov.b64 %0, {%1,%2};" : "=l"(r) : "f"(x), "f"(y)); return r;
}
__device__ __forceinline__ void fma2(u64t& d, u64t a, u64t b) {
    asm("fma.rn.f32x2 %0, %1, %2, %0;" : "+l"(d) : "l"(a), "l"(b));
}
__device__ __forceinline__ void add2(u64t& d, u64t a) {
    asm("add.rn.f32x2 %0, %0, %1;" : "+l"(d) : "l"(a));
}
__device__ __forceinline__ float tanh_fast(float x) {
    float y; asm("tanh.approx.f32 %0, %1;" : "=f"(y) : "f"(x)); return y;
}
__device__ __forceinline__ void st_cluster_b64(uint32_t addr, u64t v) {
    asm volatile("st.shared::cluster.b64 [%0], %1;" :: "r"(addr), "l"(v) : "memory");
}
__device__ __forceinline__ void arrive_release_cluster(uint32_t mb) {
    asm volatile("mbarrier.arrive.release.cluster.shared::cluster.b64 _, [%0];"
                 :: "r"(mb) : "memory");
}
__device__ __forceinline__ void mbar_wait(uint32_t mb, uint32_t par) {
    asm volatile(
        "{ .reg .pred p;\n\t"
        "WAIT_%=:\n\t"
        "  mbarrier.try_wait.parity.acquire.cluster.shared::cta.b64 p, [%0], %1, 0x989680;\n\t"
        "  @!p bra WAIT_%=;\n\t"
        "}" :: "r"(mb), "r"(par) : "memory");
}

__global__ void __cluster_dims__(CS, 1, 1) __launch_bounds__(256, 1)
ltc_scan(const float* __restrict__ Wrec, const float* __restrict__ mask,
         const float* __restrict__ tau_raw, float* __restrict__ out,
         int outoff)
{
    __shared__ __align__(16) float hb[3][CS][BLK];
    __shared__ u64t mbar[4];

    uint32_t rank;
    asm("mov.u32 %0, %%cluster_ctarank;" : "=r"(rank));
    const int cl = blockIdx.x / CS;
    const int b0 = cl * 2;
    const int b1 = b0 + 1;

    const int tid  = threadIdx.x;
    const int lane = tid & 31;
    const int warp = tid >> 5;
    const int jl   = lane & 7;      // neuron within warp
    const int ks   = lane >> 3;     // k-slice (= source rank block) 0..3
    const int j    = warp * 8 + jl; // local neuron 0..63
    const int jf   = (int)rank * 64 + j;   // global neuron 0..255

    uint32_t mb_u32[4];
    #pragma unroll
    for (int i = 0; i < 4; i++) mb_u32[i] = smem_u32(&mbar[i]);
    if (tid == 0) {
        #pragma unroll
        for (int i = 0; i < 4; i++)
            asm volatile("mbarrier.init.shared.b64 [%0], 4;" :: "r"(mb_u32[i]) : "memory");
    }

    // Zero all h buffers.
    for (int e = tid; e < 3 * CS * BLK; e += 256)
        ((float*)hb)[e] = 0.f;

    // DSMEM rank-address deltas (mapa is affine in the address).
    int32_t dsd[CS];
    #pragma unroll
    for (int c = 0; c < CS; c++) {
        uint32_t ra;
        asm("mapa.shared::cluster.u32 %0, %1, %2;" : "=r"(ra) : "r"(mb_u32[0]), "r"(c));
        dsd[c] = (int32_t)(ra - mb_u32[0]);
    }

    // 64 masked weights (k in [ks*64, ks*64+64)), duplicated (w_k, w_k).
    u64t w2[64];
    {
        const float4* wr = (const float4*)(Wrec + (size_t)jf * HH + ks * 64);
        const float4* mr = (const float4*)(mask + (size_t)jf * HH + ks * 64);
        #pragma unroll
        for (int ii = 0; ii < 16; ii++) {
            float4 wv = __ldg(wr + ii);
            float4 mv = __ldg(mr + ii);
            float w0 = wv.x * mv.x, w1 = wv.y * mv.y;
            float wq = wv.z * mv.z, w3 = wv.w * mv.w;
            w2[4 * ii + 0] = pk2(w0, w0);
            w2[4 * ii + 1] = pk2(w1, w1);
            w2[4 * ii + 2] = pk2(wq, wq);
            w2[4 * ii + 3] = pk2(w3, w3);
        }
    }

    const float tr     = tau_raw[jf];
    const float invtau = 1.0f / (log1pf(expf(tr)) + 0.1f);

    const float* xp0 = g_xp + (size_t)(b0 * TT) * HH + jf;
    const float* xp1 = g_xp + (size_t)(b1 * TT) * HH + jf;
    float* out0 = out + (size_t)(b0 * TT) * 512 + outoff + jf;
    float* out1 = out + (size_t)(b1 * TT) * 512 + outoff + jf;

    // Arrive target for this thread (tid 0..3 only): rank (rank+tid)&3.
    const int32_t arr_dsd = dsd[((int)rank + tid) & 3];

    __syncthreads();
    asm volatile("barrier.cluster.arrive.aligned;" ::: "memory");
    asm volatile("barrier.cluster.wait.aligned;"   ::: "memory");

    // Prefetch xq for t=0 (same address across ks -> L1 broadcast).
    float xq0 = __ldg(xp0);
    float xq1 = __ldg(xp1);

    int wb = 0, rb = 2;

    for (int t = 0; t < TT; t++) {
        const uint32_t mbx = mb_u32[t & 3];

        // h_old pair for this thread's neuron.
        const u64t hop = *(const u64t*)(&hb[rb][rank][2 * j]);

        // GEMV slice over source block ks: 32 LDS.128, 64 fma2.
        const ulonglong2* ph = (const ulonglong2*)(&hb[rb][ks][0]);
        u64t a0 = 0, a1 = 0, a2 = 0, a3 = 0;
        #pragma unroll
        for (int ii = 0; ii < 16; ii++) {
            ulonglong2 v0 = ph[2 * ii + 0];
            ulonglong2 v1 = ph[2 * ii + 1];
            fma2(a0, w2[4 * ii + 0], v0.x);
            fma2(a1, w2[4 * ii + 1], v0.y);
            fma2(a2, w2[4 * ii + 2], v1.x);
            fma2(a3, w2[4 * ii + 3], v1.y);
        }
        add2(a0, a1);
        add2(a2, a3);
        add2(a0, a2);
        {
            u64t ts = __shfl_xor_sync(0xffffffffu, (unsigned long long)a0, 8);
            add2(a0, ts);
            ts = __shfl_xor_sync(0xffffffffu, (unsigned long long)a0, 16);
            add2(a0, ts);
        }

        float s0, s1, h0o, h1o;
        asm("mov.b64 {%0,%1}, %2;" : "=f"(s0), "=f"(s1) : "l"(a0));
        asm("mov.b64 {%0,%1}, %2;" : "=f"(h0o), "=f"(h1o) : "l"(hop));

        float hn0 = fmaf(tanh_fast(s0 + xq0) - h0o, invtau, h0o);
        float hn1 = fmaf(tanh_fast(s1 + xq1) - h1o, invtau, h1o);

        // Producers scatter the pair to all 4 ranks (plain remote stores).
        if (ks == 0) {
            const u64t hv = pk2(hn0, hn1);
            const uint32_t la = smem_u32(&hb[wb][rank][2 * j]);
            #pragma unroll
            for (int c = 0; c < CS; c++)
                st_cluster_b64(la + dsd[c], hv);
        }
        __syncthreads();

        // One release-arrive per destination CTA (threads 0..3).
        if (tid < 4)
            arrive_release_cluster(mbx + arr_dsd);

        // Off-critical-path work while the arrives/stores fly.
        if (ks == 1) out0[(size_t)t * 512] = hn0;
        if (ks == 2) out1[(size_t)t * 512] = hn1;
        if (t + 1 < TT) {
            xq0 = __ldg(xp0 + (size_t)(t + 1) * HH);
            xq1 = __ldg(xp1 + (size_t)(t + 1) * HH);
        }

        // Wait for all 4 source CTAs' arrives for step t.
        mbar_wait(mbx, (uint32_t)((t >> 2) & 1));

        rb = wb;
        wb = (wb == 2) ? 0 : wb + 1;
    }

    // Nobody exits while peers' DSMEM stores may still target us.
    asm volatile("barrier.cluster.arrive.aligned;" ::: "memory");
    asm volatile("barrier.cluster.wait.aligned;"   ::: "memory");
}

// ---------------------------------------------------------------------------
// Launch: gemm(xp0) -> scan0 -> gemm(xp1 from h0 in d_out) -> scan1
// ---------------------------------------------------------------------------
extern "C" void kernel_launch(void* const* d_in, const int* in_sizes, int n_in,
                              void* d_out, int out_size)
{
    const int*   tokens = (const int*)  d_in[0];
    const float* emb    = (const float*)d_in[1];
    const float* W_in0  = (const float*)d_in[2];
    const float* W_rec0 = (const float*)d_in[3];
    const float* b0     = (const float*)d_in[4];
    const float* tau0   = (const float*)d_in[5];
    const float* mask0  = (const float*)d_in[6];
    const float* W_in1  = (const float*)d_in[7];
    const float* W_rec1 = (const float*)d_in[8];
    const float* b1     = (const float*)d_in[9];
    const float* tau1   = (const float*)d_in[10];
    const float* mask1  = (const float*)d_in[11];
    float* out = (float*)d_out;

    (void)in_sizes; (void)n_in; (void)out_size;

    dim3 ggrid(BT / 64, HH / 64);   // 128 x 4

    gemm_xp<<<ggrid, 256>>>(emb, tokens, EE, W_in0, b0);
    ltc_scan<<<128, 256>>>(W_rec0, mask0, tau0, out, 0);
    gemm_xp<<<ggrid, 256>>>(out, nullptr, 512, W_in1, b1);
    ltc_scan<<<128, 256>>>(W_rec1, mask1, tau1, out, 256);
}

// round 10
// speedup vs baseline: 1.4127x; 1.4127x over previous
#include <cuda_runtime.h>
#include <cstdint>
#include <math.h>

// Problem constants
#define BB   64
#define TT   128
#define EE   256
#define HH   256
#define BT   (BB*TT)        // 8192

// Scratch input-drive buffers: xp0 from the gemm, xp1 produced by scan0.
__device__ float g_xp [BT * HH];
__device__ float g_xp2[BT * HH];

// ---------------------------------------------------------------------------
// GEMM: g_xp[m, n] = sum_k A[row(m), k] * W[n, k] + bias[n]
// ---------------------------------------------------------------------------
__global__ __launch_bounds__(256) void gemm_xp(
    const float* __restrict__ A, const int* __restrict__ rowidx, int astride,
    const float* __restrict__ W, const float* __restrict__ bias)
{
    __shared__ float As[32][68];
    __shared__ float Bs[32][68];

    const int m0  = blockIdx.x * 64;
    const int n0  = blockIdx.y * 64;
    const int tid = threadIdx.x;
    const int lr  = tid >> 3;
    const int lk  = (tid & 7) << 2;
    const int ty  = tid >> 4;
    const int tx  = tid & 15;

    float acc[4][4] = {};

    for (int k0 = 0; k0 < 256; k0 += 32) {
        #pragma unroll
        for (int rr = 0; rr < 2; rr++) {
            int m  = m0 + lr + rr * 32;
            int ar = rowidx ? rowidx[m] : m;
            float4 a4 = *(const float4*)(A + (size_t)ar * astride + k0 + lk);
            As[lk + 0][lr + rr * 32] = a4.x;
            As[lk + 1][lr + rr * 32] = a4.y;
            As[lk + 2][lr + rr * 32] = a4.z;
            As[lk + 3][lr + rr * 32] = a4.w;

            int n = n0 + lr + rr * 32;
            float4 b4 = *(const float4*)(W + (size_t)n * 256 + k0 + lk);
            Bs[lk + 0][lr + rr * 32] = b4.x;
            Bs[lk + 1][lr + rr * 32] = b4.y;
            Bs[lk + 2][lr + rr * 32] = b4.z;
            Bs[lk + 3][lr + rr * 32] = b4.w;
        }
        __syncthreads();

        #pragma unroll
        for (int kk = 0; kk < 32; kk++) {
            float a[4], b[4];
            *(float4*)a = *(const float4*)&As[kk][ty << 2];
            *(float4*)b = *(const float4*)&Bs[kk][tx << 2];
            #pragma unroll
            for (int i = 0; i < 4; i++)
                #pragma unroll
                for (int jx = 0; jx < 4; jx++)
                    acc[i][jx] = fmaf(a[i], b[jx], acc[i][jx]);
        }
        __syncthreads();
    }

    float4 bv = *(const float4*)(bias + n0 + (tx << 2));
    #pragma unroll
    for (int i = 0; i < 4; i++) {
        int m = m0 + (ty << 2) + i;
        float4 o;
        o.x = acc[i][0] + bv.x;
        o.y = acc[i][1] + bv.y;
        o.z = acc[i][2] + bv.z;
        o.w = acc[i][3] + bv.w;
        *(float4*)(g_xp + (size_t)m * 256 + n0 + (tx << 2)) = o;
    }
}

// ---------------------------------------------------------------------------
// LTC scan (R4 champion skeleton): 4-CTA clusters, 32 clusters, 2 batch each.
//   - Masked recurrent weights in registers; f32x2 GEMV; tanh.approx.
//   - Exchange: STS -> bar.sync -> fence.proxy.async -> 3 bulk DSMEM copies
//     (issued by tid 0/1/2 in parallel), tx mbarrier 1536 B, 2 alternating
//     barriers, 3-buffer rotation.
//   - FUSE (scan0 only): during the fabric-wait window, compute
//     xp1(t-1) = W_in1 @ h0(t-1) + b1 from the still-resident hb[rb] and
//     store to g_xp2 — eliminates the second gemm kernel entirely.
// ---------------------------------------------------------------------------
#define CS   4
#define BLK  132     // floats per rank block: 128 data (64 b0 | 64 b1) + 4 pad

typedef unsigned long long u64t;

__device__ __forceinline__ uint32_t smem_u32(const void* p) {
    return (uint32_t)__cvta_generic_to_shared(p);
}
__device__ __forceinline__ u64t pk2(float x, float y) {
    u64t r; asm("mov.b64 %0, {%1,%2};" : "=l"(r) : "f"(x), "f"(y)); return r;
}
__device__ __forceinline__ void fma2(u64t& d, u64t a, u64t b) {
    asm("fma.rn.f32x2 %0, %1, %2, %0;" : "+l"(d) : "l"(a), "l"(b));
}
__device__ __forceinline__ float hsum2(u64t v) {
    float a, b; asm("mov.b64 {%0,%1}, %2;" : "=f"(a), "=f"(b) : "l"(v));
    return a + b;
}
__device__ __forceinline__ float tanh_fast(float x) {
    float y; asm("tanh.approx.f32 %0, %1;" : "=f"(y) : "f"(x)); return y;
}
__device__ __forceinline__ void mbar_wait(uint32_t mb, uint32_t par) {
    asm volatile(
        "{ .reg .pred p;\n\t"
        "WAIT_%=:\n\t"
        "  mbarrier.try_wait.parity.acquire.cluster.shared::cta.b64 p, [%0], %1, 0x989680;\n\t"
        "  @!p bra WAIT_%=;\n\t"
        "}" :: "r"(mb), "r"(par) : "memory");
}

template <bool FUSE>
__global__ void __cluster_dims__(CS, 1, 1) __launch_bounds__(256, 1)
ltc_scan(const float* __restrict__ Wrec, const float* __restrict__ mask,
         const float* __restrict__ tau_raw,
         const float* __restrict__ xp_in, float* __restrict__ out, int outoff,
         const float* __restrict__ Wi1, const float* __restrict__ B1,
         float* __restrict__ xp_out)
{
    __shared__ __align__(16) float hb[3][CS][BLK];
    __shared__ u64t mbar[2];

    uint32_t rank;
    asm("mov.u32 %0, %%cluster_ctarank;" : "=r"(rank));
    const int cl = blockIdx.x / CS;
    const int b0 = cl * 2;
    const int b1 = b0 + 1;

    const int tid  = threadIdx.x;
    const int lane = tid & 31;
    const int warp = tid >> 5;
    const int jl   = lane & 7;
    const int ks   = lane >> 3;
    const int j    = warp * 8 + jl;
    const int jf   = (int)rank * 64 + j;

    const uint32_t mb_u32[2] = { smem_u32(&mbar[0]), smem_u32(&mbar[1]) };
    if (tid == 0) {
        asm volatile("mbarrier.init.shared.b64 [%0], 1;" :: "r"(mb_u32[0]) : "memory");
        asm volatile("mbarrier.init.shared.b64 [%0], 1;" :: "r"(mb_u32[1]) : "memory");
    }

    for (int e = tid; e < 3 * CS * BLK; e += 256)
        ((float*)hb)[e] = 0.f;

    int32_t dsd[CS];
    #pragma unroll
    for (int c = 0; c < CS; c++) {
        uint32_t ra;
        asm("mapa.shared::cluster.u32 %0, %1, %2;" : "=r"(ra) : "r"(mb_u32[0]), "r"(c));
        dsd[c] = (int32_t)(ra - mb_u32[0]);
    }

    // Recurrent weights (masked), k in [ks*64, ks*64+64): 32 f32x2 pairs.
    u64t wa[32];
    {
        const float4* wr = (const float4*)(Wrec + (size_t)jf * HH + ks * 64);
        const float4* mr = (const float4*)(mask + (size_t)jf * HH + ks * 64);
        #pragma unroll
        for (int ii = 0; ii < 16; ii++) {
            float4 wv = __ldg(wr + ii);
            float4 mv = __ldg(mr + ii);
            wa[2 * ii + 0] = pk2(wv.x * mv.x, wv.y * mv.y);
            wa[2 * ii + 1] = pk2(wv.z * mv.z, wv.w * mv.w);
        }
    }
    // Fused level-1 input weights (scan0 only).
    u64t wi[32];
    float bias1 = 0.f;
    if (FUSE) {
        const float4* wr = (const float4*)(Wi1 + (size_t)jf * HH + ks * 64);
        #pragma unroll
        for (int ii = 0; ii < 16; ii++) {
            float4 wv = __ldg(wr + ii);
            wi[2 * ii + 0] = pk2(wv.x, wv.y);
            wi[2 * ii + 1] = pk2(wv.z, wv.w);
        }
        bias1 = __ldg(B1 + jf);
    }

    const float tr     = tau_raw[jf];
    const float invtau = 1.0f / (log1pf(expf(tr)) + 0.1f);

    const float* xp0 = xp_in + (size_t)(b0 * TT) * HH + jf;
    const float* xp1 = xp_in + (size_t)(b1 * TT) * HH + jf;
    float* out0 = out + (size_t)(b0 * TT) * 512 + outoff + jf;
    float* out1 = out + (size_t)(b1 * TT) * 512 + outoff + jf;
    float* xo0  = FUSE ? xp_out + (size_t)(b0 * TT) * HH + jf : nullptr;
    float* xo1  = FUSE ? xp_out + (size_t)(b1 * TT) * HH + jf : nullptr;

    __syncthreads();
    asm volatile("barrier.cluster.arrive.aligned;" ::: "memory");
    asm volatile("barrier.cluster.wait.aligned;"   ::: "memory");

    float xq0 = __ldg(xp0);
    float xq1 = __ldg(xp1);

    int wb = 0, rb = 2;

    for (int t = 0; t < TT; t++) {
        const uint32_t mbx = mb_u32[t & 1];
        if (tid == 0)
            asm volatile("mbarrier.arrive.expect_tx.shared.b64 _, [%0], 1536;"
                         :: "r"(mbx) : "memory");

        // h_old for this thread's neuron.
        const float* rblk = &hb[rb][rank][0];
        float h0o = rblk[j];
        float h1o = rblk[64 + j];

        // GEMV slice over source block ks (k = ks*64 .. ks*64+63).
        const ulonglong2* p0 = (const ulonglong2*)(&hb[rb][ks][0]);
        const ulonglong2* p1 = (const ulonglong2*)(&hb[rb][ks][64]);
        u64t a0 = 0, a1 = 0, c0 = 0, c1 = 0;
        #pragma unroll
        for (int ii = 0; ii < 16; ii++) {
            ulonglong2 v0 = p0[ii];
            ulonglong2 v1 = p1[ii];
            fma2(a0, wa[2 * ii + 0], v0.x);
            fma2(a1, wa[2 * ii + 1], v0.y);
            fma2(c0, wa[2 * ii + 0], v1.x);
            fma2(c1, wa[2 * ii + 1], v1.y);
        }
        float s0 = hsum2(a0) + hsum2(a1);
        float s1 = hsum2(c0) + hsum2(c1);
        s0 += __shfl_xor_sync(0xffffffffu, s0, 8);
        s0 += __shfl_xor_sync(0xffffffffu, s0, 16);
        s1 += __shfl_xor_sync(0xffffffffu, s1, 8);
        s1 += __shfl_xor_sync(0xffffffffu, s1, 16);

        float hn0 = fmaf(tanh_fast(s0 + xq0) - h0o, invtau, h0o);
        float hn1 = fmaf(tanh_fast(s1 + xq1) - h1o, invtau, h1o);

        // ks==0 lanes publish locally.
        float* wblk = &hb[wb][rank][0];
        if (ks == 0) {
            wblk[j]      = hn0;
            wblk[64 + j] = hn1;
        }
        __syncthreads();

        // tid 0/1/2 each issue one bulk copy to one peer.
        if (tid < 3) {
            asm volatile("fence.proxy.async.shared::cta;" ::: "memory");
            const uint32_t src  = smem_u32(wblk);
            const int      peer = ((int)rank + tid + 1) & 3;
            asm volatile(
                "cp.async.bulk.shared::cluster.shared::cta.mbarrier::complete_tx::bytes "
                "[%0], [%1], 512, [%2];"
                :: "r"(src + dsd[peer]), "r"(src), "r"(mbx + dsd[peer])
                : "memory");
        }

        // --- Off-critical-path work while the bulk copies fly ---
        if (ks == 1) out0[(size_t)t * 512] = hn0;
        if (ks == 2) out1[(size_t)t * 512] = hn1;
        if (t + 1 < TT) {
            xq0 = __ldg(xp0 + (size_t)(t + 1) * HH);
            xq1 = __ldg(xp1 + (size_t)(t + 1) * HH);
        }

        // Fused xp1(t-1) = W_in1 @ h0(t-1) + b1, from hb[rb] (still intact:
        // this buffer is not overwritten until step t+2 by the 3-rotation).
        if (FUSE && t > 0) {
            u64t y0 = 0, y1 = 0, z0 = 0, z1 = 0;
            #pragma unroll
            for (int ii = 0; ii < 16; ii++) {
                ulonglong2 v0 = p0[ii];
                ulonglong2 v1 = p1[ii];
                fma2(y0, wi[2 * ii + 0], v0.x);
                fma2(y1, wi[2 * ii + 1], v0.y);
                fma2(z0, wi[2 * ii + 0], v1.x);
                fma2(z1, wi[2 * ii + 1], v1.y);
            }
            float u0 = hsum2(y0) + hsum2(y1);
            float u1 = hsum2(z0) + hsum2(z1);
            u0 += __shfl_xor_sync(0xffffffffu, u0, 8);
            u0 += __shfl_xor_sync(0xffffffffu, u0, 16);
            u1 += __shfl_xor_sync(0xffffffffu, u1, 8);
            u1 += __shfl_xor_sync(0xffffffffu, u1, 16);
            if (ks == 3) {
                xo0[(size_t)(t - 1) * HH] = u0 + bias1;
                xo1[(size_t)(t - 1) * HH] = u1 + bias1;
            }
        }

        mbar_wait(mbx, (uint32_t)((t >> 1) & 1));

        rb = wb;
        wb = (wb == 2) ? 0 : wb + 1;
    }

    // Fused xp1 for the final step (hb[rb] now holds h0(TT-1)).
    if (FUSE) {
        const ulonglong2* p0 = (const ulonglong2*)(&hb[rb][ks][0]);
        const ulonglong2* p1 = (const ulonglong2*)(&hb[rb][ks][64]);
        u64t y0 = 0, y1 = 0, z0 = 0, z1 = 0;
        #pragma unroll
        for (int ii = 0; ii < 16; ii++) {
            ulonglong2 v0 = p0[ii];
            ulonglong2 v1 = p1[ii];
            fma2(y0, wi[2 * ii + 0], v0.x);
            fma2(y1, wi[2 * ii + 1], v0.y);
            fma2(z0, wi[2 * ii + 0], v1.x);
            fma2(z1, wi[2 * ii + 1], v1.y);
        }
        float u0 = hsum2(y0) + hsum2(y1);
        float u1 = hsum2(z0) + hsum2(z1);
        u0 += __shfl_xor_sync(0xffffffffu, u0, 8);
        u0 += __shfl_xor_sync(0xffffffffu, u0, 16);
        u1 += __shfl_xor_sync(0xffffffffu, u1, 8);
        u1 += __shfl_xor_sync(0xffffffffu, u1, 16);
        if (ks == 3) {
            xo0[(size_t)(TT - 1) * HH] = u0 + bias1;
            xo1[(size_t)(TT - 1) * HH] = u1 + bias1;
        }
    }

    // Nobody exits while peers' bulk reads of our SMEM may be in flight.
    asm volatile("barrier.cluster.arrive.aligned;" ::: "memory");
    asm volatile("barrier.cluster.wait.aligned;"   ::: "memory");
}

// ---------------------------------------------------------------------------
// Launch: gemm(xp0) -> scan0 (fused: also produces xp1) -> scan1
// ---------------------------------------------------------------------------
extern "C" void kernel_launch(void* const* d_in, const int* in_sizes, int n_in,
                              void* d_out, int out_size)
{
    const int*   tokens = (const int*)  d_in[0];
    const float* emb    = (const float*)d_in[1];
    const float* W_in0  = (const float*)d_in[2];
    const float* W_rec0 = (const float*)d_in[3];
    const float* b0     = (const float*)d_in[4];
    const float* tau0   = (const float*)d_in[5];
    const float* mask0  = (const float*)d_in[6];
    const float* W_in1  = (const float*)d_in[7];
    const float* W_rec1 = (const float*)d_in[8];
    const float* b1     = (const float*)d_in[9];
    const float* tau1   = (const float*)d_in[10];
    const float* mask1  = (const float*)d_in[11];
    float* out = (float*)d_out;

    (void)in_sizes; (void)n_in; (void)out_size;

    float* xp0_buf;
    float* xp1_buf;
    cudaGetSymbolAddress((void**)&xp0_buf, g_xp);
    cudaGetSymbolAddress((void**)&xp1_buf, g_xp2);

    dim3 ggrid(BT / 64, HH / 64);   // 128 x 4

    gemm_xp<<<ggrid, 256>>>(emb, tokens, EE, W_in0, b0);
    ltc_scan<true ><<<128, 256>>>(W_rec0, mask0, tau0, xp0_buf, out, 0,
                                  W_in1, b1, xp1_buf);
    ltc_scan<false><<<128, 256>>>(W_rec1, mask1, tau1, xp1_buf, out, 256,
                                  nullptr, nullptr, nullptr);
}

// round 11
// speedup vs baseline: 1.4218x; 1.0064x over previous
#include <cuda_runtime.h>
#include <cstdint>
#include <math.h>

// Problem constants
#define BB   64
#define TT   128
#define EE   256
#define HH   256
#define BT   (BB*TT)        // 8192

// Scratch input-drive buffers: xp0 from the gemm, xp1 produced by scan0.
__device__ float g_xp [BT * HH];
__device__ float g_xp2[BT * HH];

typedef unsigned long long u64t;

__device__ __forceinline__ u64t pk2(float x, float y) {
    u64t r; asm("mov.b64 %0, {%1,%2};" : "=l"(r) : "f"(x), "f"(y)); return r;
}
__device__ __forceinline__ void fma2(u64t& d, u64t a, u64t b) {
    asm("fma.rn.f32x2 %0, %1, %2, %0;" : "+l"(d) : "l"(a), "l"(b));
}
__device__ __forceinline__ void upk2(float& x, float& y, u64t v) {
    asm("mov.b64 {%0,%1}, %2;" : "=f"(x), "=f"(y) : "l"(v));
}

// ---------------------------------------------------------------------------
// GEMM: g_xp[m, n] = sum_k A[row(m), k] * W[n, k] + bias[n]
//   64x64 tile, K-chunks of 32, register double-buffered global loads,
//   f32x2 inner product (8 FFMA2 per kk instead of 16 FFMA).
// ---------------------------------------------------------------------------
__global__ __launch_bounds__(256) void gemm_xp(
    const float* __restrict__ A, const int* __restrict__ rowidx, int astride,
    const float* __restrict__ W, const float* __restrict__ bias)
{
    __shared__ float As[32][68];
    __shared__ float Bs[32][68];

    const int m0  = blockIdx.x * 64;
    const int n0  = blockIdx.y * 64;
    const int tid = threadIdx.x;
    const int lr  = tid >> 3;          // 0..31 loader row
    const int lk  = (tid & 7) << 2;    // 0,4,...,28 loader k
    const int ty  = tid >> 4;          // 0..15
    const int tx  = tid & 15;          // 0..15

    // Hoisted row gather (loop-invariant across K-chunks).
    const int m_a0 = m0 + lr;
    const int m_a1 = m0 + lr + 32;
    const int ar0  = rowidx ? rowidx[m_a0] : m_a0;
    const int ar1  = rowidx ? rowidx[m_a1] : m_a1;
    const float* ap0 = A + (size_t)ar0 * astride + lk;
    const float* ap1 = A + (size_t)ar1 * astride + lk;
    const float* bp0 = W + (size_t)(n0 + lr) * 256 + lk;
    const float* bp1 = W + (size_t)(n0 + lr + 32) * 256 + lk;

    // Prefetch chunk 0.
    float4 a4[2], b4[2];
    a4[0] = *(const float4*)(ap0);
    a4[1] = *(const float4*)(ap1);
    b4[0] = *(const float4*)(bp0);
    b4[1] = *(const float4*)(bp1);

    // acc[j][p]: column j (tx*4+j), row-pair p (rows ty*4+2p, ty*4+2p+1)
    u64t acc[4][2] = {};

    for (int k0 = 0; k0 < 256; k0 += 32) {
        // Stage current chunk into SMEM.
        As[lk + 0][lr]      = a4[0].x;
        As[lk + 1][lr]      = a4[0].y;
        As[lk + 2][lr]      = a4[0].z;
        As[lk + 3][lr]      = a4[0].w;
        As[lk + 0][lr + 32] = a4[1].x;
        As[lk + 1][lr + 32] = a4[1].y;
        As[lk + 2][lr + 32] = a4[1].z;
        As[lk + 3][lr + 32] = a4[1].w;
        Bs[lk + 0][lr]      = b4[0].x;
        Bs[lk + 1][lr]      = b4[0].y;
        Bs[lk + 2][lr]      = b4[0].z;
        Bs[lk + 3][lr]      = b4[0].w;
        Bs[lk + 0][lr + 32] = b4[1].x;
        Bs[lk + 1][lr + 32] = b4[1].y;
        Bs[lk + 2][lr + 32] = b4[1].z;
        Bs[lk + 3][lr + 32] = b4[1].w;
        __syncthreads();

        // Prefetch next chunk while computing this one.
        if (k0 < 224) {
            a4[0] = *(const float4*)(ap0 + k0 + 32);
            a4[1] = *(const float4*)(ap1 + k0 + 32);
            b4[0] = *(const float4*)(bp0 + k0 + 32);
            b4[1] = *(const float4*)(bp1 + k0 + 32);
        }

        #pragma unroll
        for (int kk = 0; kk < 32; kk++) {
            // a row-pairs (m contiguous in As) as two u64s.
            ulonglong2 ap = *(const ulonglong2*)&As[kk][ty << 2];
            float4     bf = *(const float4*)&Bs[kk][tx << 2];
            u64t bd0 = pk2(bf.x, bf.x);
            u64t bd1 = pk2(bf.y, bf.y);
            u64t bd2 = pk2(bf.z, bf.z);
            u64t bd3 = pk2(bf.w, bf.w);
            fma2(acc[0][0], bd0, ap.x);  fma2(acc[0][1], bd0, ap.y);
            fma2(acc[1][0], bd1, ap.x);  fma2(acc[1][1], bd1, ap.y);
            fma2(acc[2][0], bd2, ap.x);  fma2(acc[2][1], bd2, ap.y);
            fma2(acc[3][0], bd3, ap.x);  fma2(acc[3][1], bd3, ap.y);
        }
        __syncthreads();
    }

    // Epilogue: unpack, add bias, store.
    float4 bv = *(const float4*)(bias + n0 + (tx << 2));
    float c[4][4];   // [row in quad][col]
    #pragma unroll
    for (int jx = 0; jx < 4; jx++) {
        upk2(c[0][jx], c[1][jx], acc[jx][0]);
        upk2(c[2][jx], c[3][jx], acc[jx][1]);
    }
    #pragma unroll
    for (int i = 0; i < 4; i++) {
        int m = m0 + (ty << 2) + i;
        float4 o;
        o.x = c[i][0] + bv.x;
        o.y = c[i][1] + bv.y;
        o.z = c[i][2] + bv.z;
        o.w = c[i][3] + bv.w;
        *(float4*)(g_xp + (size_t)m * 256 + n0 + (tx << 2)) = o;
    }
}

// ---------------------------------------------------------------------------
// LTC scan (unchanged R10 champion): 4-CTA clusters, 32 clusters.
//   - Masked recurrent weights in registers; f32x2 GEMV; tanh.approx.
//   - Exchange: STS -> bar.sync -> fence.proxy.async -> 3 bulk DSMEM copies
//     (tid 0/1/2), tx mbarrier 1536 B, 2 alternating barriers, 3-buffer rot.
//   - FUSE (scan0 only): xp1(t-1) = W_in1 @ h0(t-1) + b1 computed in the
//     fabric-wait window -> g_xp2; kills the second gemm kernel.
// ---------------------------------------------------------------------------
#define CS   4
#define BLK  132     // floats per rank block: 128 data (64 b0 | 64 b1) + 4 pad

__device__ __forceinline__ uint32_t smem_u32(const void* p) {
    return (uint32_t)__cvta_generic_to_shared(p);
}
__device__ __forceinline__ float hsum2(u64t v) {
    float a, b; asm("mov.b64 {%0,%1}, %2;" : "=f"(a), "=f"(b) : "l"(v));
    return a + b;
}
__device__ __forceinline__ float tanh_fast(float x) {
    float y; asm("tanh.approx.f32 %0, %1;" : "=f"(y) : "f"(x)); return y;
}
__device__ __forceinline__ void mbar_wait(uint32_t mb, uint32_t par) {
    asm volatile(
        "{ .reg .pred p;\n\t"
        "WAIT_%=:\n\t"
        "  mbarrier.try_wait.parity.acquire.cluster.shared::cta.b64 p, [%0], %1, 0x989680;\n\t"
        "  @!p bra WAIT_%=;\n\t"
        "}" :: "r"(mb), "r"(par) : "memory");
}

template <bool FUSE>
__global__ void __cluster_dims__(CS, 1, 1) __launch_bounds__(256, 1)
ltc_scan(const float* __restrict__ Wrec, const float* __restrict__ mask,
         const float* __restrict__ tau_raw,
         const float* __restrict__ xp_in, float* __restrict__ out, int outoff,
         const float* __restrict__ Wi1, const float* __restrict__ B1,
         float* __restrict__ xp_out)
{
    __shared__ __align__(16) float hb[3][CS][BLK];
    __shared__ u64t mbar[2];

    uint32_t rank;
    asm("mov.u32 %0, %%cluster_ctarank;" : "=r"(rank));
    const int cl = blockIdx.x / CS;
    const int b0 = cl * 2;
    const int b1 = b0 + 1;

    const int tid  = threadIdx.x;
    const int lane = tid & 31;
    const int warp = tid >> 5;
    const int jl   = lane & 7;
    const int ks   = lane >> 3;
    const int j    = warp * 8 + jl;
    const int jf   = (int)rank * 64 + j;

    const uint32_t mb_u32[2] = { smem_u32(&mbar[0]), smem_u32(&mbar[1]) };
    if (tid == 0) {
        asm volatile("mbarrier.init.shared.b64 [%0], 1;" :: "r"(mb_u32[0]) : "memory");
        asm volatile("mbarrier.init.shared.b64 [%0], 1;" :: "r"(mb_u32[1]) : "memory");
    }

    for (int e = tid; e < 3 * CS * BLK; e += 256)
        ((float*)hb)[e] = 0.f;

    int32_t dsd[CS];
    #pragma unroll
    for (int c = 0; c < CS; c++) {
        uint32_t ra;
        asm("mapa.shared::cluster.u32 %0, %1, %2;" : "=r"(ra) : "r"(mb_u32[0]), "r"(c));
        dsd[c] = (int32_t)(ra - mb_u32[0]);
    }

    // Recurrent weights (masked), k in [ks*64, ks*64+64): 32 f32x2 pairs.
    u64t wa[32];
    {
        const float4* wr = (const float4*)(Wrec + (size_t)jf * HH + ks * 64);
        const float4* mr = (const float4*)(mask + (size_t)jf * HH + ks * 64);
        #pragma unroll
        for (int ii = 0; ii < 16; ii++) {
            float4 wv = __ldg(wr + ii);
            float4 mv = __ldg(mr + ii);
            wa[2 * ii + 0] = pk2(wv.x * mv.x, wv.y * mv.y);
            wa[2 * ii + 1] = pk2(wv.z * mv.z, wv.w * mv.w);
        }
    }
    // Fused level-1 input weights (scan0 only).
    u64t wi[32];
    float bias1 = 0.f;
    if (FUSE) {
        const float4* wr = (const float4*)(Wi1 + (size_t)jf * HH + ks * 64);
        #pragma unroll
        for (int ii = 0; ii < 16; ii++) {
            float4 wv = __ldg(wr + ii);
            wi[2 * ii + 0] = pk2(wv.x, wv.y);
            wi[2 * ii + 1] = pk2(wv.z, wv.w);
        }
        bias1 = __ldg(B1 + jf);
    }

    const float tr     = tau_raw[jf];
    const float invtau = 1.0f / (log1pf(expf(tr)) + 0.1f);

    const float* xp0 = xp_in + (size_t)(b0 * TT) * HH + jf;
    const float* xp1 = xp_in + (size_t)(b1 * TT) * HH + jf;
    float* out0 = out + (size_t)(b0 * TT) * 512 + outoff + jf;
    float* out1 = out + (size_t)(b1 * TT) * 512 + outoff + jf;
    float* xo0  = FUSE ? xp_out + (size_t)(b0 * TT) * HH + jf : nullptr;
    float* xo1  = FUSE ? xp_out + (size_t)(b1 * TT) * HH + jf : nullptr;

    __syncthreads();
    asm volatile("barrier.cluster.arrive.aligned;" ::: "memory");
    asm volatile("barrier.cluster.wait.aligned;"   ::: "memory");

    float xq0 = __ldg(xp0);
    float xq1 = __ldg(xp1);

    int wb = 0, rb = 2;

    for (int t = 0; t < TT; t++) {
        const uint32_t mbx = mb_u32[t & 1];
        if (tid == 0)
            asm volatile("mbarrier.arrive.expect_tx.shared.b64 _, [%0], 1536;"
                         :: "r"(mbx) : "memory");

        const float* rblk = &hb[rb][rank][0];
        float h0o = rblk[j];
        float h1o = rblk[64 + j];

        const ulonglong2* p0 = (const ulonglong2*)(&hb[rb][ks][0]);
        const ulonglong2* p1 = (const ulonglong2*)(&hb[rb][ks][64]);
        u64t a0 = 0, a1 = 0, c0 = 0, c1 = 0;
        #pragma unroll
        for (int ii = 0; ii < 16; ii++) {
            ulonglong2 v0 = p0[ii];
            ulonglong2 v1 = p1[ii];
            fma2(a0, wa[2 * ii + 0], v0.x);
            fma2(a1, wa[2 * ii + 1], v0.y);
            fma2(c0, wa[2 * ii + 0], v1.x);
            fma2(c1, wa[2 * ii + 1], v1.y);
        }
        float s0 = hsum2(a0) + hsum2(a1);
        float s1 = hsum2(c0) + hsum2(c1);
        s0 += __shfl_xor_sync(0xffffffffu, s0, 8);
        s0 += __shfl_xor_sync(0xffffffffu, s0, 16);
        s1 += __shfl_xor_sync(0xffffffffu, s1, 8);
        s1 += __shfl_xor_sync(0xffffffffu, s1, 16);

        float hn0 = fmaf(tanh_fast(s0 + xq0) - h0o, invtau, h0o);
        float hn1 = fmaf(tanh_fast(s1 + xq1) - h1o, invtau, h1o);

        float* wblk = &hb[wb][rank][0];
        if (ks == 0) {
            wblk[j]      = hn0;
            wblk[64 + j] = hn1;
        }
        __syncthreads();

        if (tid < 3) {
            asm volatile("fence.proxy.async.shared::cta;" ::: "memory");
            const uint32_t src  = smem_u32(wblk);
            const int      peer = ((int)rank + tid + 1) & 3;
            asm volatile(
                "cp.async.bulk.shared::cluster.shared::cta.mbarrier::complete_tx::bytes "
                "[%0], [%1], 512, [%2];"
                :: "r"(src + dsd[peer]), "r"(src), "r"(mbx + dsd[peer])
                : "memory");
        }

        // --- Off-critical-path work while the bulk copies fly ---
        if (ks == 1) out0[(size_t)t * 512] = hn0;
        if (ks == 2) out1[(size_t)t * 512] = hn1;
        if (t + 1 < TT) {
            xq0 = __ldg(xp0 + (size_t)(t + 1) * HH);
            xq1 = __ldg(xp1 + (size_t)(t + 1) * HH);
        }

        if (FUSE && t > 0) {
            u64t y0 = 0, y1 = 0, z0 = 0, z1 = 0;
            #pragma unroll
            for (int ii = 0; ii < 16; ii++) {
                ulonglong2 v0 = p0[ii];
                ulonglong2 v1 = p1[ii];
                fma2(y0, wi[2 * ii + 0], v0.x);
                fma2(y1, wi[2 * ii + 1], v0.y);
                fma2(z0, wi[2 * ii + 0], v1.x);
                fma2(z1, wi[2 * ii + 1], v1.y);
            }
            float u0 = hsum2(y0) + hsum2(y1);
            float u1 = hsum2(z0) + hsum2(z1);
            u0 += __shfl_xor_sync(0xffffffffu, u0, 8);
            u0 += __shfl_xor_sync(0xffffffffu, u0, 16);
            u1 += __shfl_xor_sync(0xffffffffu, u1, 8);
            u1 += __shfl_xor_sync(0xffffffffu, u1, 16);
            if (ks == 3) {
                xo0[(size_t)(t - 1) * HH] = u0 + bias1;
                xo1[(size_t)(t - 1) * HH] = u1 + bias1;
            }
        }

        mbar_wait(mbx, (uint32_t)((t >> 1) & 1));

        rb = wb;
        wb = (wb == 2) ? 0 : wb + 1;
    }

    // Fused xp1 for the final step (hb[rb] holds h0(TT-1)).
    if (FUSE) {
        const ulonglong2* p0 = (const ulonglong2*)(&hb[rb][ks][0]);
        const ulonglong2* p1 = (const ulonglong2*)(&hb[rb][ks][64]);
        u64t y0 = 0, y1 = 0, z0 = 0, z1 = 0;
        #pragma unroll
        for (int ii = 0; ii < 16; ii++) {
            ulonglong2 v0 = p0[ii];
            ulonglong2 v1 = p1[ii];
            fma2(y0, wi[2 * ii + 0], v0.x);
            fma2(y1, wi[2 * ii + 1], v0.y);
            fma2(z0, wi[2 * ii + 0], v1.x);
            fma2(z1, wi[2 * ii + 1], v1.y);
        }
        float u0 = hsum2(y0) + hsum2(y1);
        float u1 = hsum2(z0) + hsum2(z1);
        u0 += __shfl_xor_sync(0xffffffffu, u0, 8);
        u0 += __shfl_xor_sync(0xffffffffu, u0, 16);
        u1 += __shfl_xor_sync(0xffffffffu, u1, 8);
        u1 += __shfl_xor_sync(0xffffffffu, u1, 16);
        if (ks == 3) {
            xo0[(size_t)(TT - 1) * HH] = u0 + bias1;
            xo1[(size_t)(TT - 1) * HH] = u1 + bias1;
        }
    }

    asm volatile("barrier.cluster.arrive.aligned;" ::: "memory");
    asm volatile("barrier.cluster.wait.aligned;"   ::: "memory");
}

// ---------------------------------------------------------------------------
// Launch: gemm(xp0) -> scan0 (fused: also produces xp1) -> scan1
// ---------------------------------------------------------------------------
extern "C" void kernel_launch(void* const* d_in, const int* in_sizes, int n_in,
                              void* d_out, int out_size)
{
    const int*   tokens = (const int*)  d_in[0];
    const float* emb    = (const float*)d_in[1];
    const float* W_in0  = (const float*)d_in[2];
    const float* W_rec0 = (const float*)d_in[3];
    const float* b0     = (const float*)d_in[4];
    const float* tau0   = (const float*)d_in[5];
    const float* mask0  = (const float*)d_in[6];
    const float* W_in1  = (const float*)d_in[7];
    const float* W_rec1 = (const float*)d_in[8];
    const float* b1     = (const float*)d_in[9];
    const float* tau1   = (const float*)d_in[10];
    const float* mask1  = (const float*)d_in[11];
    float* out = (float*)d_out;

    (void)in_sizes; (void)n_in; (void)out_size;

    float* xp0_buf;
    float* xp1_buf;
    cudaGetSymbolAddress((void**)&xp0_buf, g_xp);
    cudaGetSymbolAddress((void**)&xp1_buf, g_xp2);

    dim3 ggrid(BT / 64, HH / 64);   // 128 x 4

    gemm_xp<<<ggrid, 256>>>(emb, tokens, EE, W_in0, b0);
    ltc_scan<true ><<<128, 256>>>(W_rec0, mask0, tau0, xp0_buf, out, 0,
                                  W_in1, b1, xp1_buf);
    ltc_scan<false><<<128, 256>>>(W_rec1, mask1, tau1, xp1_buf, out, 256,
                                  nullptr, nullptr, nullptr);
}

// round 13
// speedup vs baseline: 1.4708x; 1.0345x over previous
#include <cuda_runtime.h>
#include <cstdint>
#include <math.h>

// Problem constants
#define BB   64
#define TT   128
#define EE   256
#define HH   256
#define BT   (BB*TT)        // 8192

// Scratch input-drive buffers: xp0 from the gemm, xp1 produced by scan0.
__device__ float g_xp [BT * HH];
__device__ float g_xp2[BT * HH];

typedef unsigned long long u64t;

__device__ __forceinline__ u64t pk2(float x, float y) {
    u64t r; asm("mov.b64 %0, {%1,%2};" : "=l"(r) : "f"(x), "f"(y)); return r;
}
__device__ __forceinline__ void fma2(u64t& d, u64t a, u64t b) {
    asm("fma.rn.f32x2 %0, %1, %2, %0;" : "+l"(d) : "l"(a), "l"(b));
}
__device__ __forceinline__ void upk2(float& x, float& y, u64t v) {
    asm("mov.b64 {%0,%1}, %2;" : "=f"(x), "=f"(y) : "l"(v));
}

// ---------------------------------------------------------------------------
// GEMM: g_xp[m, n] = sum_k A[row(m), k] * W[n, k] + bias[n]
//   128x128 tile, 8x8 micro-tile (4+4 split rows/cols), K-chunks of 32,
//   register double-buffered LDG, f32x2 math. Inner loop: 4 LDS.128 +
//   8 pk2 + 32 FFMA2 per kk (1:8 LDS:FMA2 — crossbar no longer binding).
// ---------------------------------------------------------------------------
__global__ __launch_bounds__(256) void gemm_xp(
    const float* __restrict__ A, const int* __restrict__ rowidx, int astride,
    const float* __restrict__ W, const float* __restrict__ bias)
{
    __shared__ float As[32][136];
    __shared__ float Bs[32][136];

    const int m0  = blockIdx.x * 128;
    const int n0  = blockIdx.y * 128;
    const int tid = threadIdx.x;
    const int tx  = tid & 15;          // 0..15  (col group)
    const int ty  = tid >> 4;          // 0..15  (row group)

    // Loaders: each thread owns one row (lrow) and 16 consecutive k (lkq).
    const int lrow = tid >> 1;             // 0..127
    const int lkq  = (tid & 1) << 4;       // 0 or 16
    const int marow = m0 + lrow;
    const int arow  = rowidx ? rowidx[marow] : marow;
    const float* apt = A + (size_t)arow * astride + lkq;
    const float* bpt = W + (size_t)(n0 + lrow) * 256 + lkq;

    // Prefetch chunk 0 (4 float4 per matrix).
    float4 apf[4], bpf[4];
    #pragma unroll
    for (int c = 0; c < 4; c++) {
        apf[c] = *(const float4*)(apt + 4 * c);
        bpf[c] = *(const float4*)(bpt + 4 * c);
    }

    // acc[j][p]: col j (0..7), row-pair p (0..3).
    u64t acc[8][4] = {};

    for (int k0 = 0; k0 < 256; k0 += 32) {
        // Stage current chunk into SMEM (transposed to k-major).
        #pragma unroll
        for (int c = 0; c < 4; c++) {
            As[lkq + 4 * c + 0][lrow] = apf[c].x;
            As[lkq + 4 * c + 1][lrow] = apf[c].y;
            As[lkq + 4 * c + 2][lrow] = apf[c].z;
            As[lkq + 4 * c + 3][lrow] = apf[c].w;
            Bs[lkq + 4 * c + 0][lrow] = bpf[c].x;
            Bs[lkq + 4 * c + 1][lrow] = bpf[c].y;
            Bs[lkq + 4 * c + 2][lrow] = bpf[c].z;
            Bs[lkq + 4 * c + 3][lrow] = bpf[c].w;
        }
        __syncthreads();

        // Prefetch next chunk while computing this one.
        if (k0 < 224) {
            #pragma unroll
            for (int c = 0; c < 4; c++) {
                apf[c] = *(const float4*)(apt + k0 + 32 + 4 * c);
                bpf[c] = *(const float4*)(bpt + k0 + 32 + 4 * c);
            }
        }

        #pragma unroll
        for (int kk = 0; kk < 32; kk++) {
            // a row-pairs: rows {ty*4..+3} and {64+ty*4..+3} as 4 u64s.
            ulonglong2 aq0 = *(const ulonglong2*)&As[kk][ty << 2];
            ulonglong2 aq1 = *(const ulonglong2*)&As[kk][64 + (ty << 2)];
            // b cols: {tx*4..+3} and {64+tx*4..+3}.
            float4 bf0 = *(const float4*)&Bs[kk][tx << 2];
            float4 bf1 = *(const float4*)&Bs[kk][64 + (tx << 2)];

            u64t bd[8];
            bd[0] = pk2(bf0.x, bf0.x); bd[1] = pk2(bf0.y, bf0.y);
            bd[2] = pk2(bf0.z, bf0.z); bd[3] = pk2(bf0.w, bf0.w);
            bd[4] = pk2(bf1.x, bf1.x); bd[5] = pk2(bf1.y, bf1.y);
            bd[6] = pk2(bf1.z, bf1.z); bd[7] = pk2(bf1.w, bf1.w);

            #pragma unroll
            for (int jx = 0; jx < 8; jx++) {
                fma2(acc[jx][0], bd[jx], aq0.x);
                fma2(acc[jx][1], bd[jx], aq0.y);
                fma2(acc[jx][2], bd[jx], aq1.x);
                fma2(acc[jx][3], bd[jx], aq1.y);
            }
        }
        __syncthreads();
    }

    // Epilogue: unpack pairs, add bias, store 8 rows x 2 float4.
    float4 bv0 = *(const float4*)(bias + n0 + (tx << 2));
    float4 bv1 = *(const float4*)(bias + n0 + 64 + (tx << 2));

    #pragma unroll
    for (int p = 0; p < 4; p++) {
        const int rbase = ((p >> 1) << 6) + (ty << 2) + ((p & 1) << 1);
        float v0[8], v1[8];
        #pragma unroll
        for (int jx = 0; jx < 8; jx++)
            upk2(v0[jx], v1[jx], acc[jx][p]);

        float4 o;
        float* d0 = g_xp + (size_t)(m0 + rbase) * 256 + n0;
        o.x = v0[0] + bv0.x; o.y = v0[1] + bv0.y;
        o.z = v0[2] + bv0.z; o.w = v0[3] + bv0.w;
        *(float4*)(d0 + (tx << 2)) = o;
        o.x = v0[4] + bv1.x; o.y = v0[5] + bv1.y;
        o.z = v0[6] + bv1.z; o.w = v0[7] + bv1.w;
        *(float4*)(d0 + 64 + (tx << 2)) = o;

        float* d1 = d0 + 256;
        o.x = v1[0] + bv0.x; o.y = v1[1] + bv0.y;
        o.z = v1[2] + bv0.z; o.w = v1[3] + bv0.w;
        *(float4*)(d1 + (tx << 2)) = o;
        o.x = v1[4] + bv1.x; o.y = v1[5] + bv1.y;
        o.z = v1[6] + bv1.z; o.w = v1[7] + bv1.w;
        *(float4*)(d1 + 64 + (tx << 2)) = o;
    }
}

// ---------------------------------------------------------------------------
// LTC scan (unchanged R10/R11 champion): 4-CTA clusters, 32 clusters.
//   - Masked recurrent weights in registers; f32x2 GEMV; tanh.approx.
//   - Exchange: STS -> bar.sync -> fence.proxy.async -> 3 bulk DSMEM copies
//     (tid 0/1/2), tx mbarrier 1536 B, 2 alternating barriers, 3-buffer rot.
//   - FUSE (scan0 only): xp1(t-1) = W_in1 @ h0(t-1) + b1 computed in the
//     fabric-wait window -> g_xp2; kills the second gemm kernel.
// ---------------------------------------------------------------------------
#define CS   4
#define BLK  132     // floats per rank block: 128 data (64 b0 | 64 b1) + 4 pad

__device__ __forceinline__ uint32_t smem_u32(const void* p) {
    return (uint32_t)__cvta_generic_to_shared(p);
}
__device__ __forceinline__ float hsum2(u64t v) {
    float a, b; asm("mov.b64 {%0,%1}, %2;" : "=f"(a), "=f"(b) : "l"(v));
    return a + b;
}
__device__ __forceinline__ float tanh_fast(float x) {
    float y; asm("tanh.approx.f32 %0, %1;" : "=f"(y) : "f"(x)); return y;
}
__device__ __forceinline__ void mbar_wait(uint32_t mb, uint32_t par) {
    asm volatile(
        "{ .reg .pred p;\n\t"
        "WAIT_%=:\n\t"
        "  mbarrier.try_wait.parity.acquire.cluster.shared::cta.b64 p, [%0], %1, 0x989680;\n\t"
        "  @!p bra WAIT_%=;\n\t"
        "}" :: "r"(mb), "r"(par) : "memory");
}

template <bool FUSE>
__global__ void __cluster_dims__(CS, 1, 1) __launch_bounds__(256, 1)
ltc_scan(const float* __restrict__ Wrec, const float* __restrict__ mask,
         const float* __restrict__ tau_raw,
         const float* __restrict__ xp_in, float* __restrict__ out, int outoff,
         const float* __restrict__ Wi1, const float* __restrict__ B1,
         float* __restrict__ xp_out)
{
    __shared__ __align__(16) float hb[3][CS][BLK];
    __shared__ u64t mbar[2];

    uint32_t rank;
    asm("mov.u32 %0, %%cluster_ctarank;" : "=r"(rank));
    const int cl = blockIdx.x / CS;
    const int b0 = cl * 2;
    const int b1 = b0 + 1;

    const int tid  = threadIdx.x;
    const int lane = tid & 31;
    const int warp = tid >> 5;
    const int jl   = lane & 7;
    const int ks   = lane >> 3;
    const int j    = warp * 8 + jl;
    const int jf   = (int)rank * 64 + j;

    const uint32_t mb_u32[2] = { smem_u32(&mbar[0]), smem_u32(&mbar[1]) };
    if (tid == 0) {
        asm volatile("mbarrier.init.shared.b64 [%0], 1;" :: "r"(mb_u32[0]) : "memory");
        asm volatile("mbarrier.init.shared.b64 [%0], 1;" :: "r"(mb_u32[1]) : "memory");
    }

    for (int e = tid; e < 3 * CS * BLK; e += 256)
        ((float*)hb)[e] = 0.f;

    int32_t dsd[CS];
    #pragma unroll
    for (int c = 0; c < CS; c++) {
        uint32_t ra;
        asm("mapa.shared::cluster.u32 %0, %1, %2;" : "=r"(ra) : "r"(mb_u32[0]), "r"(c));
        dsd[c] = (int32_t)(ra - mb_u32[0]);
    }

    // Recurrent weights (masked), k in [ks*64, ks*64+64): 32 f32x2 pairs.
    u64t wa[32];
    {
        const float4* wr = (const float4*)(Wrec + (size_t)jf * HH + ks * 64);
        const float4* mr = (const float4*)(mask + (size_t)jf * HH + ks * 64);
        #pragma unroll
        for (int ii = 0; ii < 16; ii++) {
            float4 wv = __ldg(wr + ii);
            float4 mv = __ldg(mr + ii);
            wa[2 * ii + 0] = pk2(wv.x * mv.x, wv.y * mv.y);
            wa[2 * ii + 1] = pk2(wv.z * mv.z, wv.w * mv.w);
        }
    }
    // Fused level-1 input weights (scan0 only).
    u64t wi[32];
    float bias1 = 0.f;
    if (FUSE) {
        const float4* wr = (const float4*)(Wi1 + (size_t)jf * HH + ks * 64);
        #pragma unroll
        for (int ii = 0; ii < 16; ii++) {
            float4 wv = __ldg(wr + ii);
            wi[2 * ii + 0] = pk2(wv.x, wv.y);
            wi[2 * ii + 1] = pk2(wv.z, wv.w);
        }
        bias1 = __ldg(B1 + jf);
    }

    const float tr     = tau_raw[jf];
    const float invtau = 1.0f / (log1pf(expf(tr)) + 0.1f);

    const float* xp0 = xp_in + (size_t)(b0 * TT) * HH + jf;
    const float* xp1 = xp_in + (size_t)(b1 * TT) * HH + jf;
    float* out0 = out + (size_t)(b0 * TT) * 512 + outoff + jf;
    float* out1 = out + (size_t)(b1 * TT) * 512 + outoff + jf;
    float* xo0  = FUSE ? xp_out + (size_t)(b0 * TT) * HH + jf : nullptr;
    float* xo1  = FUSE ? xp_out + (size_t)(b1 * TT) * HH + jf : nullptr;

    __syncthreads();
    asm volatile("barrier.cluster.arrive.aligned;" ::: "memory");
    asm volatile("barrier.cluster.wait.aligned;"   ::: "memory");

    float xq0 = __ldg(xp0);
    float xq1 = __ldg(xp1);

    int wb = 0, rb = 2;

    for (int t = 0; t < TT; t++) {
        const uint32_t mbx = mb_u32[t & 1];
        if (tid == 0)
            asm volatile("mbarrier.arrive.expect_tx.shared.b64 _, [%0], 1536;"
                         :: "r"(mbx) : "memory");

        const float* rblk = &hb[rb][rank][0];
        float h0o = rblk[j];
        float h1o = rblk[64 + j];

        const ulonglong2* p0 = (const ulonglong2*)(&hb[rb][ks][0]);
        const ulonglong2* p1 = (const ulonglong2*)(&hb[rb][ks][64]);
        u64t a0 = 0, a1 = 0, c0 = 0, c1 = 0;
        #pragma unroll
        for (int ii = 0; ii < 16; ii++) {
            ulonglong2 v0 = p0[ii];
            ulonglong2 v1 = p1[ii];
            fma2(a0, wa[2 * ii + 0], v0.x);
            fma2(a1, wa[2 * ii + 1], v0.y);
            fma2(c0, wa[2 * ii + 0], v1.x);
            fma2(c1, wa[2 * ii + 1], v1.y);
        }
        float s0 = hsum2(a0) + hsum2(a1);
        float s1 = hsum2(c0) + hsum2(c1);
        s0 += __shfl_xor_sync(0xffffffffu, s0, 8);
        s0 += __shfl_xor_sync(0xffffffffu, s0, 16);
        s1 += __shfl_xor_sync(0xffffffffu, s1, 8);
        s1 += __shfl_xor_sync(0xffffffffu, s1, 16);

        float hn0 = fmaf(tanh_fast(s0 + xq0) - h0o, invtau, h0o);
        float hn1 = fmaf(tanh_fast(s1 + xq1) - h1o, invtau, h1o);

        float* wblk = &hb[wb][rank][0];
        if (ks == 0) {
            wblk[j]      = hn0;
            wblk[64 + j] = hn1;
        }
        __syncthreads();

        if (tid < 3) {
            asm volatile("fence.proxy.async.shared::cta;" ::: "memory");
            const uint32_t src  = smem_u32(wblk);
            const int      peer = ((int)rank + tid + 1) & 3;
            asm volatile(
                "cp.async.bulk.shared::cluster.shared::cta.mbarrier::complete_tx::bytes "
                "[%0], [%1], 512, [%2];"
                :: "r"(src + dsd[peer]), "r"(src), "r"(mbx + dsd[peer])
                : "memory");
        }

        // --- Off-critical-path work while the bulk copies fly ---
        if (ks == 1) out0[(size_t)t * 512] = hn0;
        if (ks == 2) out1[(size_t)t * 512] = hn1;
        if (t + 1 < TT) {
            xq0 = __ldg(xp0 + (size_t)(t + 1) * HH);
            xq1 = __ldg(xp1 + (size_t)(t + 1) * HH);
        }

        if (FUSE && t > 0) {
            u64t y0 = 0, y1 = 0, z0 = 0, z1 = 0;
            #pragma unroll
            for (int ii = 0; ii < 16; ii++) {
                ulonglong2 v0 = p0[ii];
                ulonglong2 v1 = p1[ii];
                fma2(y0, wi[2 * ii + 0], v0.x);
                fma2(y1, wi[2 * ii + 1], v0.y);
                fma2(z0, wi[2 * ii + 0], v1.x);
                fma2(z1, wi[2 * ii + 1], v1.y);
            }
            float u0 = hsum2(y0) + hsum2(y1);
            float u1 = hsum2(z0) + hsum2(z1);
            u0 += __shfl_xor_sync(0xffffffffu, u0, 8);
            u0 += __shfl_xor_sync(0xffffffffu, u0, 16);
            u1 += __shfl_xor_sync(0xffffffffu, u1, 8);
            u1 += __shfl_xor_sync(0xffffffffu, u1, 16);
            if (ks == 3) {
                xo0[(size_t)(t - 1) * HH] = u0 + bias1;
                xo1[(size_t)(t - 1) * HH] = u1 + bias1;
            }
        }

        mbar_wait(mbx, (uint32_t)((t >> 1) & 1));

        rb = wb;
        wb = (wb == 2) ? 0 : wb + 1;
    }

    // Fused xp1 for the final step (hb[rb] holds h0(TT-1)).
    if (FUSE) {
        const ulonglong2* p0 = (const ulonglong2*)(&hb[rb][ks][0]);
        const ulonglong2* p1 = (const ulonglong2*)(&hb[rb][ks][64]);
        u64t y0 = 0, y1 = 0, z0 = 0, z1 = 0;
        #pragma unroll
        for (int ii = 0; ii < 16; ii++) {
            ulonglong2 v0 = p0[ii];
            ulonglong2 v1 = p1[ii];
            fma2(y0, wi[2 * ii + 0], v0.x);
            fma2(y1, wi[2 * ii + 1], v0.y);
            fma2(z0, wi[2 * ii + 0], v1.x);
            fma2(z1, wi[2 * ii + 1], v1.y);
        }
        float u0 = hsum2(y0) + hsum2(y1);
        float u1 = hsum2(z0) + hsum2(z1);
        u0 += __shfl_xor_sync(0xffffffffu, u0, 8);
        u0 += __shfl_xor_sync(0xffffffffu, u0, 16);
        u1 += __shfl_xor_sync(0xffffffffu, u1, 8);
        u1 += __shfl_xor_sync(0xffffffffu, u1, 16);
        if (ks == 3) {
            xo0[(size_t)(TT - 1) * HH] = u0 + bias1;
            xo1[(size_t)(TT - 1) * HH] = u1 + bias1;
        }
    }

    asm volatile("barrier.cluster.arrive.aligned;" ::: "memory");
    asm volatile("barrier.cluster.wait.aligned;"   ::: "memory");
}

// ---------------------------------------------------------------------------
// Launch: gemm(xp0) -> scan0 (fused: also produces xp1) -> scan1
// ---------------------------------------------------------------------------
extern "C" void kernel_launch(void* const* d_in, const int* in_sizes, int n_in,
                              void* d_out, int out_size)
{
    const int*   tokens = (const int*)  d_in[0];
    const float* emb    = (const float*)d_in[1];
    const float* W_in0  = (const float*)d_in[2];
    const float* W_rec0 = (const float*)d_in[3];
    const float* b0     = (const float*)d_in[4];
    const float* tau0   = (const float*)d_in[5];
    const float* mask0  = (const float*)d_in[6];
    const float* W_in1  = (const float*)d_in[7];
    const float* W_rec1 = (const float*)d_in[8];
    const float* b1     = (const float*)d_in[9];
    const float* tau1   = (const float*)d_in[10];
    const float* mask1  = (const float*)d_in[11];
    float* out = (float*)d_out;

    (void)in_sizes; (void)n_in; (void)out_size;

    float* xp0_buf;
    float* xp1_buf;
    cudaGetSymbolAddress((void**)&xp0_buf, g_xp);
    cudaGetSymbolAddress((void**)&xp1_buf, g_xp2);

    dim3 ggrid(BT / 128, HH / 128);   // 64 x 2 = 128 CTAs (one wave)

    gemm_xp<<<ggrid, 256>>>(emb, tokens, EE, W_in0, b0);
    ltc_scan<true ><<<128, 256>>>(W_rec0, mask0, tau0, xp0_buf, out, 0,
                                  W_in1, b1, xp1_buf);
    ltc_scan<false><<<128, 256>>>(W_rec1, mask1, tau1, xp1_buf, out, 256,
                                  nullptr, nullptr, nullptr);
}